// round 15
// baseline (speedup 1.0000x reference)
#include <cuda_runtime.h>
#include <math.h>

// ---------------- problem constants ----------------
#define NCLS   80
#define NTGT   512
#define NA     3
#define NB     16

#define HW0    6400   // 80x80
#define HW1    1600   // 40x40
#define HW2    400    // 20x20
#define CELLS0 (NB*NA*HW0)   // 307200
#define CELLS1 (NB*NA*HW1)   // 76800
#define CELLS2 (NB*NA*HW2)   // 19200
#define CELLS_TOTAL (CELLS0+CELLS1+CELLS2)  // 403200

#define PAIRS_PER_LEVEL (NA*NTGT)            // 1536
#define PAIRS_TOTAL     (3*PAIRS_PER_LEVEL)  // 4608

// compaction: 32 pairs per entry block (anchor-uniform: 512/32 = 16 blocks/anchor)
#define P_PER_BLOCK   32
#define QMAX          (P_PER_BLOCK*3)                 // 96
#define ENTRY_BLOCKS  (PAIRS_TOTAL/P_PER_BLOCK)       // 144
#define BLOCKS_PER_LEVEL (PAIRS_PER_LEVEL/P_PER_BLOCK) // 48

// dense obj pass in float4 units
#define OBJ4_0      (CELLS0/4)          // 76800  -> obj block 300 boundary (exact)
#define OBJ4_01     ((CELLS0+CELLS1)/4) // 96000  -> obj block 375 boundary (exact)
#define OBJ4_TOTAL  (CELLS_TOTAL/4)     // 100800
#define OBJ_BLOCKS  ((OBJ4_TOTAL + 255)/256)   // 394
#define TOTAL_BLOCKS (ENTRY_BLOCKS + OBJ_BLOCKS)

// ---------------- persistent scratch (zero-init at load; kernel restores zeros) ----
// per level: [box_sum, cnt, cls_sum, obj_sum(softplus - x*g)]
__device__ double       g_acc[12];
__device__ unsigned int g_done;

__constant__ float c_anchors[3][NA][2] = {
    {{10.f,13.f},{16.f,30.f},{33.f,23.f}},
    {{30.f,61.f},{62.f,45.f},{59.f,119.f}},
    {{116.f,90.f},{156.f,198.f},{373.f,326.f}}
};

__device__ __forceinline__ float softplus_fast(float x) {    // bce(x, 0)
    return fmaxf(x, 0.f) + __logf(1.0f + __expf(-fabsf(x)));
}
__device__ __forceinline__ float bce_fast(float x, float z) {
    return fmaxf(x, 0.f) - x * z + __logf(1.0f + __expf(-fabsf(x)));
}
__device__ __forceinline__ float sigmoidf_(float x) {
    return 1.f / (1.f + __expf(-x));
}

// ================= single kernel, two block populations =================
__global__ void __launch_bounds__(256)
yolo_fused_kernel(const float* __restrict__ p0,
                  const float* __restrict__ p1,
                  const float* __restrict__ p2,
                  const float* __restrict__ tgt,
                  float* __restrict__ out) {
    if (blockIdx.x < ENTRY_BLOCKS) {
        // ======== entry blocks: eval-compact-gather ========
        __shared__ int   q_off[QMAX];
        __shared__ float q_gx[QMAX], q_gy[QMAX];   // unclipped gxy residuals
        __shared__ float q_tw[QMAX], q_th[QMAX];
        __shared__ int   q_ci[QMAX];
        __shared__ int   s_n;
        __shared__ double s_acc[4];   // box, cnt, cls, obj-corr

        if (threadIdx.x < 4) s_acc[threadIdx.x] = 0.0;
        if (threadIdx.x == 0) s_n = 0;
        __syncthreads();

        // block-uniform: level, anchor, target range
        int level = blockIdx.x / BLOCKS_PER_LEVEL;
        int lb    = blockIdx.x % BLOCKS_PER_LEVEL;
        int a     = lb / (NTGT / P_PER_BLOCK);           // 16 blocks per anchor
        int n0    = (lb % (NTGT / P_PER_BLOCK)) * P_PER_BLOCK;

        int Wd, HW;
        const float* layer;
        if (level == 0)      { Wd = 80; HW = HW0; layer = p0; }
        else if (level == 1) { Wd = 40; HW = HW1; layer = p1; }
        else                 { Wd = 20; HW = HW2; layer = p2; }
        float Wf = (float)Wd;
        float aw = c_anchors[level][a][0];
        float ah = c_anchors[level][a][1];

        // ---- Phase 1: eval 32 pairs (warp 0 lanes), push valid cells ----
        if (threadIdx.x < P_PER_BLOCK) {
            int n = n0 + threadIdx.x;
            const float* t = tgt + n * 6;
            float tx = t[2] * Wf;
            float ty = t[3] * Wf;
            float tw = t[4] * Wf;
            float th = t[5] * Wf;

            float rw = tw / aw, rh = th / ah;
            float mr = fmaxf(fmaxf(rw, 1.f / rw), fmaxf(rh, 1.f / rh));
            if (mr < 4.0f) {
                int im = (int)t[0];
                int ci = (int)t[1];
                int rowbase = (im * 255 + a * 85) * HW;

                float xmod = fmodf(tx, 1.0f);
                float ymod = fmodf(ty, 1.0f);
                float offx_ = 0.f, offy_ = 0.f;
                bool hasx = false, hasy = false;
                if (xmod < 0.5f) { if (tx > 1.0f)      { hasx = true; offx_ =  0.5f; } }
                else             { if (tx < Wf - 1.0f) { hasx = true; offx_ = -0.5f; } }
                if (ymod < 0.5f) { if (ty > 1.0f)      { hasy = true; offy_ =  0.5f; } }
                else             { if (ty < Wf - 1.0f) { hasy = true; offy_ = -0.5f; } }

                bool  vld[3] = {true, hasx, hasy};
                float ofx[3] = {0.f, offx_, 0.f};
                float ofy[3] = {0.f, 0.f,  offy_};
                #pragma unroll
                for (int s = 0; s < 3; s++) {
                    if (vld[s]) {
                        int grid_x = (int)(tx - ofx[s]);
                        int grid_y = (int)(ty - ofy[s]);
                        int gxc = min(max(grid_x, 0), Wd - 1);
                        int gyc = min(max(grid_y, 0), Wd - 1);
                        int slot = atomicAdd(&s_n, 1);
                        q_off[slot] = rowbase + gyc * Wd + gxc;
                        q_gx[slot]  = tx - (float)grid_x;   // unclipped residual
                        q_gy[slot]  = ty - (float)grid_y;
                        q_tw[slot]  = tw;
                        q_th[slot]  = th;
                        q_ci[slot]  = ci;
                    }
                }
            }
        }
        __syncthreads();

        // ---- Phase 2: all 8 warps drain the queue, 2 cells per iteration ----
        int nc   = s_n;
        int lane = threadIdx.x & 31;
        int warp = threadIdx.x >> 5;

        double bsum = 0.0, clsum = 0.0, ocsum = 0.0;
        int cnt = 0;

        for (int base = warp * 2; base < nc; base += 16) {
            int i0 = base;
            int i1 = base + 1;
            bool has1 = (i1 < nc);

            int off0_ = q_off[i0];
            int off1_ = has1 ? q_off[i1] : off0_;
            int ci0 = q_ci[i0];
            int ci1 = has1 ? q_ci[i1] : 0;

            // issue all 6 gather LDGs up front
            float a0 = layer[(size_t)off0_ + (size_t)lane * HW];
            float a1 = layer[(size_t)off0_ + (size_t)(lane + 32) * HW];
            float a2 = (lane < 21) ? layer[(size_t)off0_ + (size_t)(lane + 64) * HW] : 0.f;
            float b0 = 0.f, b1 = 0.f, b2 = 0.f;
            if (has1) {
                b0 = layer[(size_t)off1_ + (size_t)lane * HW];
                b1 = layer[(size_t)off1_ + (size_t)(lane + 32) * HW];
                b2 = (lane < 21) ? layer[(size_t)off1_ + (size_t)(lane + 64) * HW] : 0.f;
            }

            // class bce for both cells, fused butterfly
            float csA = 0.f, csB = 0.f;
            if (lane >= 5) csA += bce_fast(a0, (lane - 5 == ci0) ? 1.0f : 0.0f);
            csA += bce_fast(a1, (lane + 27 == ci0) ? 1.0f : 0.0f);
            if (lane < 21) csA += bce_fast(a2, (lane + 59 == ci0) ? 1.0f : 0.0f);
            if (has1) {
                if (lane >= 5) csB += bce_fast(b0, (lane - 5 == ci1) ? 1.0f : 0.0f);
                csB += bce_fast(b1, (lane + 27 == ci1) ? 1.0f : 0.0f);
                if (lane < 21) csB += bce_fast(b2, (lane + 59 == ci1) ? 1.0f : 0.0f);
            }
            #pragma unroll
            for (int sh = 16; sh > 0; sh >>= 1) {
                csA += __shfl_xor_sync(0xffffffffu, csA, sh);
                csB += __shfl_xor_sync(0xffffffffu, csB, sh);
            }

            // broadcast box/obj logits (channels 0..4 live in lanes 0..4 of *0)
            float A0 = __shfl_sync(0xffffffffu, a0, 0);
            float A1 = __shfl_sync(0xffffffffu, a0, 1);
            float A2 = __shfl_sync(0xffffffffu, a0, 2);
            float A3 = __shfl_sync(0xffffffffu, a0, 3);
            float A4 = __shfl_sync(0xffffffffu, a0, 4);
            float B0 = __shfl_sync(0xffffffffu, b0, 0);
            float B1 = __shfl_sync(0xffffffffu, b0, 1);
            float B2 = __shfl_sync(0xffffffffu, b0, 2);
            float B3 = __shfl_sync(0xffffffffu, b0, 3);
            float B4 = __shfl_sync(0xffffffffu, b0, 4);

            if (lane == 0) {
                #pragma unroll
                for (int s = 0; s < 2; s++) {
                    if (s == 1 && !has1) break;
                    int   idx = (s == 0) ? i0 : i1;
                    float o0  = (s == 0) ? A0 : B0;
                    float o1  = (s == 0) ? A1 : B1;
                    float o2  = (s == 0) ? A2 : B2;
                    float o3  = (s == 0) ? A3 : B3;
                    float oo  = (s == 0) ? A4 : B4;
                    float cs  = (s == 0) ? csA : csB;
                    float gxx = q_gx[idx];
                    float gyy = q_gy[idx];
                    float tww = q_tw[idx];
                    float thh = q_th[idx];

                    float px = sigmoidf_(o0) * 2.0f - 0.5f;
                    float py = sigmoidf_(o1) * 2.0f - 0.5f;
                    float sw = sigmoidf_(o2) * 2.0f;
                    float sh2 = sigmoidf_(o3) * 2.0f;
                    float pw = sw * sw * aw;
                    float ph = sh2 * sh2 * ah;

                    float ax0 = px - pw * 0.5f, ax1 = px + pw * 0.5f;
                    float ay0 = py - ph * 0.5f, ay1 = py + ph * 0.5f;
                    float bx0 = gxx - tww * 0.5f, bx1 = gxx + tww * 0.5f;
                    float by0 = gyy - thh * 0.5f, by1 = gyy + thh * 0.5f;
                    float iw = fmaxf(fminf(ax1, bx1) - fmaxf(ax0, bx0), 0.0f);
                    float ih = fmaxf(fminf(ay1, by1) - fmaxf(ay0, by0), 0.0f);
                    float inter = iw * ih;
                    float uni = (ax1 - ax0) * (ay1 - ay0) + (bx1 - bx0) * (by1 - by0) - inter;
                    float iou = inter / uni;
                    float cw = fmaxf(ax1, bx1) - fminf(ax0, bx0) + 1e-16f;
                    float ch = fmaxf(ay1, by1) - fminf(ay0, by0);
                    float carea = cw * ch + 1e-16f;
                    float giou = iou - (carea - uni) / carea;

                    float gval = fmaxf(giou, 0.0f);
                    bsum  += (double)(1.0f - giou);
                    clsum += (double)cs;
                    ocsum += -(double)oo * (double)gval;   // bce(x,g)-bce(x,0)
                    cnt++;
                }
            }
        }

        if (lane == 0 && cnt > 0) {
            atomicAdd(&s_acc[0], bsum);
            atomicAdd(&s_acc[1], (double)cnt);
            atomicAdd(&s_acc[2], clsum);
            atomicAdd(&s_acc[3], ocsum);
        }
        __syncthreads();
        if (threadIdx.x == 0 && s_acc[1] != 0.0) {
            atomicAdd(&g_acc[level * 4 + 0], s_acc[0]);
            atomicAdd(&g_acc[level * 4 + 1], s_acc[1]);
            atomicAdd(&g_acc[level * 4 + 2], s_acc[2]);
            atomicAdd(&g_acc[level * 4 + 3], s_acc[3]);
        }
    } else {
        // ---- dense objectness: Σ softplus(obj_logit), float4-vectorized ----
        __shared__ float s_part[8];
        int ob = blockIdx.x - ENTRY_BLOCKS;
        int i4 = ob * 256 + threadIdx.x;
        float s = 0.f;
        if (i4 < OBJ4_TOTAL) {
            int cell4, HW4;
            const float* layer;
            if (i4 < OBJ4_0)       { cell4 = i4;           HW4 = HW0/4; layer = p0; }
            else if (i4 < OBJ4_01) { cell4 = i4 - OBJ4_0;  HW4 = HW1/4; layer = p1; }
            else                   { cell4 = i4 - OBJ4_01; HW4 = HW2/4; layer = p2; }
            int b   = cell4 / (NA * HW4);
            int r   = cell4 % (NA * HW4);
            int a   = r / HW4;
            int hw4 = r % HW4;
            const float4* ptr = (const float4*)(layer) + (size_t)(b * 255 + a * 85 + 4) * HW4 + hw4;
            float4 v = *ptr;
            s = softplus_fast(v.x) + softplus_fast(v.y) + softplus_fast(v.z) + softplus_fast(v.w);
        }
        #pragma unroll
        for (int sh = 16; sh > 0; sh >>= 1)
            s += __shfl_xor_sync(0xffffffffu, s, sh);
        int lane = threadIdx.x & 31;
        int warp = threadIdx.x >> 5;
        if (lane == 0) s_part[warp] = s;
        __syncthreads();
        if (warp == 0) {
            float bsum = (lane < 8) ? s_part[lane] : 0.f;
            #pragma unroll
            for (int sh = 4; sh > 0; sh >>= 1)
                bsum += __shfl_xor_sync(0xffffffffu, bsum, sh);
            if (lane == 0) {
                int olvl = (ob < OBJ4_0/256) ? 0 : ((ob < OBJ4_01/256) ? 1 : 2);
                atomicAdd(&g_acc[olvl * 4 + 3], (double)bsum);
            }
        }
    }

    // ---- last-block ticket: finalize + reset ----
    if (threadIdx.x == 0) {
        __threadfence();
        unsigned int ticket = atomicAdd(&g_done, 1u);
        if (ticket == (unsigned int)(TOTAL_BLOCKS - 1)) {
            volatile double* acc = g_acc;
            const double bal[3]   = {4.0, 1.0, 0.4};
            const double cells[3] = {(double)CELLS0, (double)CELLS1, (double)CELLS2};
            double lbox = 0.0, lobj = 0.0, lcls = 0.0;
            for (int l = 0; l < 3; l++) {
                double cnt = acc[l * 4 + 1];
                if (cnt > 0.0) {
                    lbox += acc[l * 4 + 0] / cnt;
                    lcls += acc[l * 4 + 2] / (cnt * (double)NCLS);
                }
                lobj += bal[l] * (acc[l * 4 + 3] / cells[l]);
            }
            double loss = (0.05 * lbox + 1.0 * lobj + 0.5 * lcls) * (double)NB;
            out[0] = (float)loss;

            for (int i = 0; i < 12; i++) g_acc[i] = 0.0;
            g_done = 0u;
        }
    }
}

// ---------------- launch ----------------
extern "C" void kernel_launch(void* const* d_in, const int* in_sizes, int n_in,
                              void* d_out, int out_size) {
    const float* p0  = (const float*)d_in[0];
    const float* p1  = (const float*)d_in[1];
    const float* p2  = (const float*)d_in[2];
    const float* tgt = (const float*)d_in[3];
    float* out = (float*)d_out;

    yolo_fused_kernel<<<TOTAL_BLOCKS, 256>>>(p0, p1, p2, tgt, out);
}

// round 17
// speedup vs baseline: 1.5702x; 1.5702x over previous
#include <cuda_runtime.h>
#include <math.h>
#include <stdint.h>

// ---------------- problem constants ----------------
#define NCLS   80
#define NTGT   512
#define NA     3
#define NB     16

#define HW0    6400   // 80x80
#define HW1    1600   // 40x40
#define HW2    400    // 20x20
#define CELLS0 (NB*NA*HW0)   // 307200
#define CELLS1 (NB*NA*HW1)   // 76800
#define CELLS2 (NB*NA*HW2)   // 19200
#define CELLS_TOTAL (CELLS0+CELLS1+CELLS2)  // 403200

// two warps per (level, anchor, target): sub0 = {off0, offx}, sub1 = {offy}
#define PAIRS_PER_LEVEL (NA*NTGT)            // 1536
#define PAIRS_TOTAL     (3*PAIRS_PER_LEVEL)  // 4608
#define ENTRY_WARPS     (2*PAIRS_TOTAL)      // 9216
#define ENTRY_BLOCKS    (ENTRY_WARPS/8)      // 1152 (level boundaries at 384/768, exact)

// dense obj pass in float4 units
#define OBJ4_0      (CELLS0/4)          // 76800  -> obj block 300 boundary (exact)
#define OBJ4_01     ((CELLS0+CELLS1)/4) // 96000  -> obj block 375 boundary (exact)
#define OBJ4_TOTAL  (CELLS_TOTAL/4)     // 100800
#define OBJ_BLOCKS  ((OBJ4_TOTAL + 255)/256)   // 394
#define TOTAL_BLOCKS (ENTRY_BLOCKS + OBJ_BLOCKS)

// ---------------- persistent scratch (zero-init at load; kernel restores zeros) ----
// per level: [box_sum, cnt, cls_sum, obj_sum(softplus - x*g)]
__device__ double       g_acc[12];
__device__ unsigned int g_done;

__constant__ float c_anchors[3][NA][2] = {
    {{10.f,13.f},{16.f,30.f},{33.f,23.f}},
    {{30.f,61.f},{62.f,45.f},{59.f,119.f}},
    {{116.f,90.f},{156.f,198.f},{373.f,326.f}}
};

__device__ __forceinline__ float softplus_fast(float x) {    // bce(x, 0)
    return fmaxf(x, 0.f) + __logf(1.0f + __expf(-fabsf(x)));
}
__device__ __forceinline__ float bce_fast(float x, float z) {
    return fmaxf(x, 0.f) - x * z + __logf(1.0f + __expf(-fabsf(x)));
}
__device__ __forceinline__ float sigmoidf_(float x) {
    return 1.f / (1.f + __expf(-x));
}

// L2 evict_last via cache-policy descriptor (valid ptxas path on sm_103a)
__device__ __forceinline__ uint64_t mk_policy_el() {
    uint64_t pol;
    asm("createpolicy.fractional.L2::evict_last.b64 %0, 1.0;" : "=l"(pol));
    return pol;
}
__device__ __forceinline__ float ldg_el(const float* p, uint64_t pol) {
    float v;
    asm("ld.global.nc.L2::cache_hint.f32 %0, [%1], %2;" : "=f"(v) : "l"(p), "l"(pol));
    return v;
}
__device__ __forceinline__ float4 ldg_el4(const float4* p, uint64_t pol) {
    float4 v;
    asm("ld.global.nc.L2::cache_hint.v4.f32 {%0,%1,%2,%3}, [%4], %5;"
        : "=f"(v.x), "=f"(v.y), "=f"(v.z), "=f"(v.w) : "l"(p), "l"(pol));
    return v;
}

// ================= single kernel, two block populations =================
__global__ void __launch_bounds__(256)
yolo_fused_kernel(const float* __restrict__ p0,
                  const float* __restrict__ p1,
                  const float* __restrict__ p2,
                  const float* __restrict__ tgt,
                  float* __restrict__ out) {
    uint64_t pol = mk_policy_el();

    if (blockIdx.x < ENTRY_BLOCKS) {
        // ---- entry: TWO warps per (level, anchor, target) ----
        __shared__ double s_acc[4];   // box, cnt, cls, obj-corr
        if (threadIdx.x < 4) s_acc[threadIdx.x] = 0.0;
        __syncthreads();

        int gwid = blockIdx.x * 8 + (threadIdx.x >> 5);
        int lane = threadIdx.x & 31;
        int pair = gwid >> 1;
        int sub  = gwid & 1;          // 0: {off0, offx}; 1: {offy}

        int level = pair / PAIRS_PER_LEVEL;
        int rem   = pair % PAIRS_PER_LEVEL;
        int a = rem / NTGT;
        int n = rem % NTGT;

        int Wd, HW;
        const float* layer;
        if (level == 0)      { Wd = 80; HW = HW0; layer = p0; }
        else if (level == 1) { Wd = 40; HW = HW1; layer = p1; }
        else                 { Wd = 20; HW = HW2; layer = p2; }
        float Wf = (float)Wd;

        const float* t = tgt + n * 6;
        float tx = ldg_el(t + 2, pol) * Wf;
        float ty = ldg_el(t + 3, pol) * Wf;
        float tw = ldg_el(t + 4, pol) * Wf;
        float th = ldg_el(t + 5, pol) * Wf;

        float aw = c_anchors[level][a][0];
        float ah = c_anchors[level][a][1];

        float rw = tw / aw, rh = th / ah;
        float mr = fmaxf(fmaxf(rw, 1.f / rw), fmaxf(rh, 1.f / rh));
        bool sel = (mr < 4.0f);      // warp-uniform

        // resolve this warp's cells (≤2): validA/validB, offsets
        bool validA = false, validB = false;
        float ofxA = 0.f, ofyA = 0.f, ofxB = 0.f, ofyB = 0.f;
        if (sel) {
            float xmod = fmodf(tx, 1.0f);
            float ymod = fmodf(ty, 1.0f);
            if (sub == 0) {
                validA = true;                       // offset 0
                if (xmod < 0.5f) { if (tx > 1.0f)      { validB = true; ofxB =  0.5f; } }
                else             { if (tx < Wf - 1.0f) { validB = true; ofxB = -0.5f; } }
            } else {
                if (ymod < 0.5f) { if (ty > 1.0f)      { validA = true; ofyA =  0.5f; } }
                else             { if (ty < Wf - 1.0f) { validA = true; ofyA = -0.5f; } }
            }
        }

        if (validA) {   // warp-uniform
            int im = (int)ldg_el(t + 0, pol);
            int ci = (int)ldg_el(t + 1, pol);
            const float* basep = layer + (size_t)((im * 255 + a * 85) * HW);

            // cell A
            int gxa_ = (int)(tx - ofxA), gya_ = (int)(ty - ofyA);
            float gxyxA = tx - (float)gxa_;
            float gxyyA = ty - (float)gya_;
            const float* cpA = basep + min(max(gya_, 0), Wd - 1) * Wd + min(max(gxa_, 0), Wd - 1);

            // cell B (x-shift; shares sectors with A most of the time)
            int gxb_ = (int)(tx - ofxB), gyb_ = (int)(ty - ofyB);
            float gxyxB = tx - (float)gxb_;
            float gxyyB = ty - (float)gyb_;
            const float* cpB = basep + min(max(gyb_, 0), Wd - 1) * Wd + min(max(gxb_, 0), Wd - 1);

            // ---- issue ALL gather loads up front ----
            float a0, a1, a2, b0 = 0.f, b1 = 0.f, b2 = 0.f;
            a0 = ldg_el(cpA + (size_t)lane * HW, pol);
            a1 = ldg_el(cpA + (size_t)(lane + 32) * HW, pol);
            a2 = (lane < 21) ? ldg_el(cpA + (size_t)(lane + 64) * HW, pol) : 0.f;
            if (validB) {
                b0 = ldg_el(cpB + (size_t)lane * HW, pol);
                b1 = ldg_el(cpB + (size_t)(lane + 32) * HW, pol);
                b2 = (lane < 21) ? ldg_el(cpB + (size_t)(lane + 64) * HW, pol) : 0.f;
            }

            // ---- class bce, fused butterfly reduce for both cells ----
            float csA = 0.f, csB = 0.f;
            if (lane >= 5) csA += bce_fast(a0, (lane - 5 == ci) ? 1.0f : 0.0f);
            csA += bce_fast(a1, (lane + 27 == ci) ? 1.0f : 0.0f);
            if (lane < 21) csA += bce_fast(a2, (lane + 59 == ci) ? 1.0f : 0.0f);
            if (validB) {
                if (lane >= 5) csB += bce_fast(b0, (lane - 5 == ci) ? 1.0f : 0.0f);
                csB += bce_fast(b1, (lane + 27 == ci) ? 1.0f : 0.0f);
                if (lane < 21) csB += bce_fast(b2, (lane + 59 == ci) ? 1.0f : 0.0f);
            }
            #pragma unroll
            for (int sh = 16; sh > 0; sh >>= 1) {
                csA += __shfl_xor_sync(0xffffffffu, csA, sh);
                csB += __shfl_xor_sync(0xffffffffu, csB, sh);
            }

            // broadcast box/obj logits (channels 0..4 in lanes 0..4 of *0)
            float A0 = __shfl_sync(0xffffffffu, a0, 0);
            float A1 = __shfl_sync(0xffffffffu, a0, 1);
            float A2 = __shfl_sync(0xffffffffu, a0, 2);
            float A3 = __shfl_sync(0xffffffffu, a0, 3);
            float A4 = __shfl_sync(0xffffffffu, a0, 4);
            float B0 = __shfl_sync(0xffffffffu, b0, 0);
            float B1 = __shfl_sync(0xffffffffu, b0, 1);
            float B2 = __shfl_sync(0xffffffffu, b0, 2);
            float B3 = __shfl_sync(0xffffffffu, b0, 3);
            float B4 = __shfl_sync(0xffffffffu, b0, 4);

            if (lane == 0) {
                double bsum = 0.0, clsum = 0.0, ocsum = 0.0;
                int cnt = 0;
                #pragma unroll
                for (int s = 0; s < 2; s++) {
                    bool v   = (s == 0) ? true  : validB;
                    if (!v) break;
                    float o0 = (s == 0) ? A0 : B0;
                    float o1 = (s == 0) ? A1 : B1;
                    float o2 = (s == 0) ? A2 : B2;
                    float o3 = (s == 0) ? A3 : B3;
                    float oo = (s == 0) ? A4 : B4;
                    float gxx = (s == 0) ? gxyxA : gxyxB;
                    float gyy = (s == 0) ? gxyyA : gxyyB;
                    float cs  = (s == 0) ? csA : csB;

                    float px = sigmoidf_(o0) * 2.0f - 0.5f;
                    float py = sigmoidf_(o1) * 2.0f - 0.5f;
                    float sw = sigmoidf_(o2) * 2.0f;
                    float sh2 = sigmoidf_(o3) * 2.0f;
                    float pw = sw * sw * aw;
                    float ph = sh2 * sh2 * ah;

                    float ax0 = px - pw * 0.5f, ax1 = px + pw * 0.5f;
                    float ay0 = py - ph * 0.5f, ay1 = py + ph * 0.5f;
                    float bx0 = gxx - tw * 0.5f, bx1 = gxx + tw * 0.5f;
                    float by0 = gyy - th * 0.5f, by1 = gyy + th * 0.5f;
                    float iw = fmaxf(fminf(ax1, bx1) - fmaxf(ax0, bx0), 0.0f);
                    float ih = fmaxf(fminf(ay1, by1) - fmaxf(ay0, by0), 0.0f);
                    float inter = iw * ih;
                    float uni = (ax1 - ax0) * (ay1 - ay0) + (bx1 - bx0) * (by1 - by0) - inter;
                    float iou = inter / uni;
                    float cw = fmaxf(ax1, bx1) - fminf(ax0, bx0) + 1e-16f;
                    float ch = fmaxf(ay1, by1) - fminf(ay0, by0);
                    float carea = cw * ch + 1e-16f;
                    float giou = iou - (carea - uni) / carea;

                    float gval = fmaxf(giou, 0.0f);
                    bsum  += (double)(1.0f - giou);
                    clsum += (double)cs;
                    ocsum += -(double)oo * (double)gval;   // bce(x,g)-bce(x,0)
                    cnt++;
                }
                atomicAdd(&s_acc[0], bsum);
                atomicAdd(&s_acc[1], (double)cnt);
                atomicAdd(&s_acc[2], clsum);
                atomicAdd(&s_acc[3], ocsum);
            }
        }
        __syncthreads();
        if (threadIdx.x == 0 && s_acc[1] != 0.0) {
            atomicAdd(&g_acc[level * 4 + 0], s_acc[0]);
            atomicAdd(&g_acc[level * 4 + 1], s_acc[1]);
            atomicAdd(&g_acc[level * 4 + 2], s_acc[2]);
            atomicAdd(&g_acc[level * 4 + 3], s_acc[3]);
        }
    } else {
        // ---- dense objectness: Σ softplus(obj_logit), float4-vectorized ----
        __shared__ float s_part[8];
        int ob = blockIdx.x - ENTRY_BLOCKS;
        int i4 = ob * 256 + threadIdx.x;
        float s = 0.f;
        if (i4 < OBJ4_TOTAL) {
            int cell4, HW4;
            const float* layer;
            if (i4 < OBJ4_0)       { cell4 = i4;           HW4 = HW0/4; layer = p0; }
            else if (i4 < OBJ4_01) { cell4 = i4 - OBJ4_0;  HW4 = HW1/4; layer = p1; }
            else                   { cell4 = i4 - OBJ4_01; HW4 = HW2/4; layer = p2; }
            int b   = cell4 / (NA * HW4);
            int r   = cell4 % (NA * HW4);
            int a   = r / HW4;
            int hw4 = r % HW4;
            float4 v = ldg_el4((const float4*)(layer) + (size_t)(b * 255 + a * 85 + 4) * HW4 + hw4, pol);
            s = softplus_fast(v.x) + softplus_fast(v.y) + softplus_fast(v.z) + softplus_fast(v.w);
        }
        #pragma unroll
        for (int sh = 16; sh > 0; sh >>= 1)
            s += __shfl_xor_sync(0xffffffffu, s, sh);
        int lane = threadIdx.x & 31;
        int warp = threadIdx.x >> 5;
        if (lane == 0) s_part[warp] = s;
        __syncthreads();
        if (warp == 0) {
            float bsum = (lane < 8) ? s_part[lane] : 0.f;
            #pragma unroll
            for (int sh = 4; sh > 0; sh >>= 1)
                bsum += __shfl_xor_sync(0xffffffffu, bsum, sh);
            if (lane == 0) {
                int olvl = (ob < OBJ4_0/256) ? 0 : ((ob < OBJ4_01/256) ? 1 : 2);
                atomicAdd(&g_acc[olvl * 4 + 3], (double)bsum);
            }
        }
    }

    // ---- last-block ticket: finalize + reset ----
    if (threadIdx.x == 0) {
        __threadfence();
        unsigned int ticket = atomicAdd(&g_done, 1u);
        if (ticket == (unsigned int)(TOTAL_BLOCKS - 1)) {
            volatile double* acc = g_acc;
            const double bal[3]   = {4.0, 1.0, 0.4};
            const double cells[3] = {(double)CELLS0, (double)CELLS1, (double)CELLS2};
            double lbox = 0.0, lobj = 0.0, lcls = 0.0;
            for (int l = 0; l < 3; l++) {
                double cnt = acc[l * 4 + 1];
                if (cnt > 0.0) {
                    lbox += acc[l * 4 + 0] / cnt;
                    lcls += acc[l * 4 + 2] / (cnt * (double)NCLS);
                }
                lobj += bal[l] * (acc[l * 4 + 3] / cells[l]);
            }
            double loss = (0.05 * lbox + 1.0 * lobj + 0.5 * lcls) * (double)NB;
            out[0] = (float)loss;

            for (int i = 0; i < 12; i++) g_acc[i] = 0.0;
            g_done = 0u;
        }
    }
}

// ---------------- launch ----------------
extern "C" void kernel_launch(void* const* d_in, const int* in_sizes, int n_in,
                              void* d_out, int out_size) {
    const float* p0  = (const float*)d_in[0];
    const float* p1  = (const float*)d_in[1];
    const float* p2  = (const float*)d_in[2];
    const float* tgt = (const float*)d_in[3];
    float* out = (float*)d_out;

    yolo_fused_kernel<<<TOTAL_BLOCKS, 256>>>(p0, p1, p2, tgt, out);
}